// round 16
// baseline (speedup 1.0000x reference)
#include <cuda_runtime.h>
#include <cuda_fp16.h>
#include <cstdint>
#include <float.h>

#define CDIM 256
#define HW   4096
#define NVEC 65536
#define NE   1024
#define LOSS_OFF 16777216
#define IDX_OFF  16777217
#define TAU      2.5e-4f     // fp32 gap-ambiguity threshold (proven R9-R15)
#define TAU_SCAN 4e-4f       // candidate scan limit vs fp16-dumped s (superset)

// ---------------- scratch ----------------
__device__ __half d_zh[(size_t)NVEC * CDIM];
__device__ __half d_ch[NE * CDIM];
__device__ __half d_sh[(size_t)NVEC * NE];   // fp16 s matrix (128MB)
__device__ float d_cnorm[NE];
__device__ float d_zn[NVEC];
__device__ float d_smin[NVEC];
__device__ int   d_sidx[NVEC];
__device__ int   d_cand[(size_t)NVEC * 48];
__device__ int   d_amb[NVEC];
__device__ int   d_count;
__device__ double d_part[256];

// ---------------- PTX helpers ----------------
__device__ __forceinline__ unsigned smem_u32(const void* p) {
    return (unsigned)__cvta_generic_to_shared(p);
}
__device__ __forceinline__ void cp_async16(unsigned s, const void* g) {
    asm volatile("cp.async.cg.shared.global [%0], [%1], 16;\n" :: "r"(s), "l"(g));
}
__device__ __forceinline__ void cp_commit() {
    asm volatile("cp.async.commit_group;\n" ::: "memory");
}
__device__ __forceinline__ void cp_wait0() {
    asm volatile("cp.async.wait_group 0;\n" ::: "memory");
}
__device__ __forceinline__ void ldsm4(unsigned* r, unsigned addr) {
    asm volatile("ldmatrix.sync.aligned.m8n8.x4.shared.b16 {%0,%1,%2,%3}, [%4];"
                 : "=r"(r[0]), "=r"(r[1]), "=r"(r[2]), "=r"(r[3]) : "r"(addr));
}
__device__ __forceinline__ void mma16816(float* d, const unsigned* a,
                                         unsigned b0, unsigned b1) {
    asm volatile(
        "mma.sync.aligned.m16n8k16.row.col.f32.f16.f16.f32 "
        "{%0,%1,%2,%3}, {%4,%5,%6,%7}, {%8,%9}, {%0,%1,%2,%3};"
        : "+f"(d[0]), "+f"(d[1]), "+f"(d[2]), "+f"(d[3])
        : "r"(a[0]), "r"(a[1]), "r"(a[2]), "r"(a[3]), "r"(b0), "r"(b1));
}
__device__ __forceinline__ void stg_cs32(void* p, unsigned v) {
    asm volatile("st.global.cs.b32 [%0], %1;" :: "l"(p), "r"(v) : "memory");
}

__device__ __forceinline__ void ins2(float s, int j, float& v0, int& i0,
                                     float& v1, int& i1) {
    if (s < v0 || (s == v0 && j < i0)) { v1 = v0; i1 = i0; v0 = s; i0 = j; }
    else if (s < v1 || (s == v1 && j < i1)) { v1 = s; i1 = j; }
}

// ---------------- prep: codebook fp16 + exact norms + zeroing --------------
__global__ void k_prep(const float* __restrict__ cb) {
    __shared__ float rowv[256];
    int j = blockIdx.x, k = threadIdx.x;
    float v = cb[j * CDIM + k];
    rowv[k] = v;
    d_ch[j * CDIM + k] = __float2half(v);
    int idx = j * 256 + k;
    if (idx < NVEC) d_zn[idx] = 0.f;
    if (idx == 0) d_count = 0;
    if (j == 0) d_part[k] = 0.0;
    __syncthreads();
    if (k == 0) {                       // exact sequential chain, ascending k
        float s = 0.f;
        for (int kk = 0; kk < CDIM; ++kk)
            s = __fadd_rn(s, __fmul_rn(rowv[kk], rowv[kk]));
        d_cnorm[j] = s;
    }
}

// ---------------- kernel: z transpose -> fp16 [i][k], fused znorm ----------
__global__ void k_convert(const float* __restrict__ z) {
    __shared__ float t[32][33];
    int k0 = blockIdx.x * 32, p0 = blockIdx.y * 32, b = blockIdx.z;
    int x = threadIdx.x, y = threadIdx.y;
#pragma unroll
    for (int yy = y; yy < 32; yy += 8)
        t[yy][x] = z[((size_t)b << 20) + ((size_t)(k0 + yy) << 12) + p0 + x];
    __syncthreads();
#pragma unroll
    for (int yy = y; yy < 32; yy += 8) {
        float v = t[x][yy];
        size_t i = ((size_t)b << 12) + p0 + yy;
        d_zh[i * CDIM + k0 + x] = __float2half(v);
        float sq = v * v;
#pragma unroll
        for (int o = 16; o; o >>= 1) sq += __shfl_xor_sync(0xffffffffu, sq, o);
        if (x == 0) atomicAdd(&d_zn[i], sq);
    }
}

// ---------------- main: fp16 HMMA + s dump + fused top-2 + loss partial ----
#define SM_A   0u
#define SM_B   32768u      // 2 x 16KB
#define SM_RED 65536u
#define SM_TOTAL 66560

__device__ __forceinline__ void stageB(int tid, int g, unsigned dstb) {
    const int ntc = g >> 2, kcc = g & 3;
#pragma unroll
    for (int q = 0; q < 8; ++q) {
        int u = q * 128 + tid;
        int r = u >> 3, w = u & 7;
        unsigned dst = (unsigned)(r * 128 + ((w * 16) ^ ((r & 7) << 4)));
        cp_async16(dstb + dst, d_ch + (size_t)(ntc * 128 + r) * CDIM + kcc * 64 + w * 8);
    }
}

__global__ __launch_bounds__(128, 3) void k_main_mma() {
    extern __shared__ __align__(128) char smem[];
    const unsigned sb = smem_u32(smem);
    const int tid = threadIdx.x, wid = tid >> 5, lane = tid & 31;
    const int m0 = blockIdx.x * 64;
    const int mb = (wid >> 1) * 32;
    const int nb = (wid & 1) * 64;

    // ---- hoisted swizzled LDSM offsets ----
    unsigned aOff0[4], aOff1[4], bOff[4][4];
    {
        const unsigned hiA = (unsigned)((lane >> 4) << 4);
        const int ar0 = mb + (lane & 15);
        const int ar1 = ar0 + 16;
#pragma unroll
        for (int ks = 0; ks < 4; ++ks) {
            aOff0[ks] = (unsigned)(ar0 * 512) + (((unsigned)(ks * 32) + hiA) ^ ((unsigned)(ar0 & 7) << 4));
            aOff1[ks] = (unsigned)(ar1 * 512) + (((unsigned)(ks * 32) + hiA) ^ ((unsigned)(ar1 & 7) << 4));
        }
        const unsigned hiB = (unsigned)(((lane >> 3) & 1) << 4);
#pragma unroll
        for (int p = 0; p < 4; ++p) {
            int br = nb + p * 16 + (lane & 7) + ((lane >> 4) << 3);
#pragma unroll
            for (int ks = 0; ks < 4; ++ks)
                bOff[p][ks] = (unsigned)(br * 128) + (((unsigned)(ks * 32) + hiB) ^ ((unsigned)(br & 7) << 4));
        }
    }

    // prologue: A (64 rows x 512B) + B chunk0
#pragma unroll
    for (int q = 0; q < 16; ++q) {
        int u = q * 128 + tid;
        int r = u >> 5, w = u & 31;
        unsigned dst = (unsigned)(r * 512 + ((w * 16) ^ ((r & 7) << 4)));
        cp_async16(sb + SM_A + dst, d_zh + (size_t)(m0 + r) * CDIM + w * 8);
    }
    stageB(tid, 0, sb + SM_B);
    cp_commit();

    __half* sOutBase = d_sh + (size_t)(m0 + mb + (lane >> 2)) * NE + nb + (lane & 3) * 2;

    float gv0[4], gv1[4];
    int   gi0[4], gi1[4];
#pragma unroll
    for (int q = 0; q < 4; ++q) {
        gv0[q] = FLT_MAX; gv1[q] = FLT_MAX;
        gi0[q] = 0x7fffffff; gi1[q] = 0x7fffffff;
    }

    float acc[2][8][4];
#pragma unroll
    for (int m = 0; m < 2; ++m)
#pragma unroll
        for (int f = 0; f < 8; ++f)
#pragma unroll
            for (int e = 0; e < 4; ++e) acc[m][f][e] = 0.f;

    for (int g = 0; g < 32; ++g) {
        cp_wait0();
        __syncthreads();
        if (g + 1 < 32) {
            stageB(tid, g + 1, sb + SM_B + (unsigned)((g + 1) & 1) * 16384u);
            cp_commit();
        }

        const unsigned aB = sb + (unsigned)((g & 3) * 128);
        const unsigned bB = sb + SM_B + (unsigned)((g & 1) * 16384);
#pragma unroll
        for (int ks = 0; ks < 4; ++ks) {
            unsigned af[8], bf[16];
            ldsm4(af,     aB + aOff0[ks]);
            ldsm4(af + 4, aB + aOff1[ks]);
#pragma unroll
            for (int p = 0; p < 4; ++p)
                ldsm4(bf + p * 4, bB + bOff[p][ks]);
#pragma unroll
            for (int p = 0; p < 4; ++p) {
                mma16816(acc[0][2 * p],     af,     bf[p * 4],     bf[p * 4 + 1]);
                mma16816(acc[0][2 * p + 1], af,     bf[p * 4 + 2], bf[p * 4 + 3]);
                mma16816(acc[1][2 * p],     af + 4, bf[p * 4],     bf[p * 4 + 1]);
                mma16816(acc[1][2 * p + 1], af + 4, bf[p * 4 + 2], bf[p * 4 + 3]);
            }
        }

        if ((g & 3) == 3) {
            const int j0 = (g >> 2) * 128;
            float cn0[8], cn1[8];
            int   colf[8];
#pragma unroll
            for (int f = 0; f < 8; ++f) {
                int col = j0 + nb + (f >> 1) * 16 + (f & 1) * 8 + (lane & 3) * 2;
                colf[f] = col;
                cn0[f] = __ldg(&d_cnorm[col]);
                cn1[f] = __ldg(&d_cnorm[col + 1]);
            }
#pragma unroll
            for (int m = 0; m < 2; ++m) {
#pragma unroll
                for (int hl = 0; hl < 2; ++hl) {
                    const int q = m * 2 + hl;
                    __half* ro = sOutBase + (size_t)(m * 16 + hl * 8) * NE + j0;
#pragma unroll
                    for (int f = 0; f < 8; ++f) {
                        float s0 = __fmaf_rn(-2.f, acc[m][f][hl * 2 + 0], cn0[f]);
                        float s1 = __fmaf_rn(-2.f, acc[m][f][hl * 2 + 1], cn1[f]);
                        __half2 h2 = __floats2half2_rn(s0, s1);
                        stg_cs32(ro + (f >> 1) * 16 + (f & 1) * 8,
                                 *(unsigned*)&h2);
                        ins2(s0, colf[f],     gv0[q], gi0[q], gv1[q], gi1[q]);
                        ins2(s1, colf[f] + 1, gv0[q], gi0[q], gv1[q], gi1[q]);
                    }
                }
            }
#pragma unroll
            for (int m = 0; m < 2; ++m)
#pragma unroll
                for (int f = 0; f < 8; ++f)
#pragma unroll
                    for (int e = 0; e < 4; ++e) acc[m][f][e] = 0.f;
        }
    }

    // ---- quad merge (lanes sharing a row) ----
#pragma unroll
    for (int q = 0; q < 4; ++q) {
#pragma unroll
        for (int o = 1; o <= 2; o <<= 1) {
            float w0 = __shfl_xor_sync(0xffffffffu, gv0[q], o);
            int   wi0 = __shfl_xor_sync(0xffffffffu, gi0[q], o);
            float w1 = __shfl_xor_sync(0xffffffffu, gv1[q], o);
            int   wi1 = __shfl_xor_sync(0xffffffffu, gi1[q], o);
            ins2(w0, wi0, gv0[q], gi0[q], gv1[q], gi1[q]);
            ins2(w1, wi1, gv0[q], gi0[q], gv1[q], gi1[q]);
        }
    }

    // ---- cross-warp (N-half) merge via smem (64 rows) + loss partial ----
    float* rv0 = (float*)(smem + SM_RED);
    float* rv1 = rv0 + 64;
    int*   ri0 = (int*)(rv1 + 64);
    int*   ri1 = ri0 + 64;
    __syncthreads();
    if ((wid & 1) == 1 && (lane & 3) == 0) {
#pragma unroll
        for (int q = 0; q < 4; ++q) {
            int rl = mb + (q >> 1) * 16 + (q & 1) * 8 + (lane >> 2);
            rv0[rl] = gv0[q]; ri0[rl] = gi0[q];
            rv1[rl] = gv1[q]; ri1[rl] = gi1[q];
        }
    }
    __syncthreads();
    if ((wid & 1) == 0 && (lane & 3) == 0) {
        double lsum = 0.0;
#pragma unroll
        for (int q = 0; q < 4; ++q) {
            int rl = mb + (q >> 1) * 16 + (q & 1) * 8 + (lane >> 2);
            ins2(rv0[rl], ri0[rl], gv0[q], gi0[q], gv1[q], gi1[q]);
            ins2(rv1[rl], ri1[rl], gv0[q], gi0[q], gv1[q], gi1[q]);
            int row = m0 + rl;
            d_smin[row] = gv0[q];
            d_sidx[row] = gi0[q];
            lsum += (double)d_zn[row] + (double)gv0[q];
            if (gv1[q] - gv0[q] < TAU)
                d_amb[atomicAdd(&d_count, 1)] = row;
        }
        atomicAdd(&d_part[blockIdx.x & 255], lsum);
    }
}

// ---------------- rescore: grid-stride; smem-staged z + exact chains -------
// Per row: warp loads all 256 z values with full MLP (independent scattered
// loads), stages them in smem, then runs the bit-exact sequential chains from
// broadcast LDS. Values identical to reading global directly (R9-R15 path).
// Updates d_sidx ONLY (d_smin keeps approx value for the loss).
__global__ void k_rescore(const float* __restrict__ z, const float* __restrict__ cb) {
    __shared__ float zrow[8][256];               // 8 warps per block
    const int lane = threadIdx.x & 31;
    const int wslot = threadIdx.x >> 5;
    const int warp0 = (blockIdx.x * blockDim.x + threadIdx.x) >> 5;
    const int nwarps = (gridDim.x * blockDim.x) >> 5;
    const int cnt = d_count;

    for (int wi = warp0; wi < cnt; wi += nwarps) {
        int row = d_amb[wi];
        int b = row >> 12, p = row & 4095;
        const float* zbase = z + ((size_t)b << 20) + p;

        // ---- stage z row: 8 independent scattered loads per lane ----
#pragma unroll
        for (int t = 0; t < 8; ++t)
            zrow[wslot][lane + t * 32] = zbase[(size_t)(lane + t * 32) << 12];
        __syncwarp();

        // ---- compact candidates: all j with s_fp16 < smin + TAU_SCAN ----
        {
            const float limit = d_smin[row] + TAU_SCAN;
            const __half2* srow = (const __half2*)(d_sh + (size_t)row * NE);
            const int winner = d_sidx[row];
            int base = 0;
#pragma unroll
            for (int it = 0; it < 16; ++it) {
                float2 s2 = __half22float2(srow[it * 32 + lane]);
#pragma unroll
                for (int e = 0; e < 2; ++e) {
                    bool take = (e ? s2.y : s2.x) < limit;
                    unsigned msk = __ballot_sync(0xffffffffu, take);
                    int pos = base + __popc(msk & ((1u << lane) - 1u));
                    if (take && pos < 48)
                        d_cand[(size_t)row * 48 + pos] = (it * 32 + lane) * 2 + e;
                    base += __popc(msk);
                }
            }
            if (base > 48) base = 48;
            for (int q = base + lane; q < 48; q += 32)
                d_cand[(size_t)row * 48 + q] = winner;
            __syncwarp();
        }

        int ja = d_cand[(size_t)row * 48 + lane] & 1023;
        int jb = (lane < 16) ? (d_cand[(size_t)row * 48 + 32 + lane] & 1023) : ja;
        const float* ca = cb + (size_t)ja * CDIM;
        const float* cbr = cb + (size_t)jb * CDIM;

        float zn = 0.f, da = 0.f, db = 0.f;
#pragma unroll 4
        for (int k = 0; k < CDIM; ++k) {        // strictly ascending k
            float zv = zrow[wslot][k];          // broadcast LDS
            zn = __fadd_rn(zn, __fmul_rn(zv, zv));
            da = __fmaf_rn(zv, ca[k], da);
            db = __fmaf_rn(zv, cbr[k], db);
        }
        float ea = __fadd_rn(__fadd_rn(zn, d_cnorm[ja]), -(2.0f * da));
        float eb = __fadd_rn(__fadd_rn(zn, d_cnorm[jb]), -(2.0f * db));

        float v = ea; int vi = ja;
        if (lane < 16 && (eb < v || (eb == v && jb < vi))) { v = eb; vi = jb; }
#pragma unroll
        for (int o = 16; o; o >>= 1) {
            float v2 = __shfl_xor_sync(0xffffffffu, v, o);
            int   i2 = __shfl_xor_sync(0xffffffffu, vi, o);
            if (v2 < v || (v2 == v && i2 < vi)) { v = v2; vi = i2; }
        }
        if (lane == 0) {
            d_sidx[row] = vi;
        }
        __syncwarp();                            // zrow WAR before next row
    }
}

// ---------------- loss final (fp64 partials from k_main) ----------------
__global__ void k_loss2(float* __restrict__ out) {
    __shared__ double sh[256];
    const int t = threadIdx.x;
    sh[t] = d_part[t];
    __syncthreads();
#pragma unroll
    for (int o = 128; o; o >>= 1) {
        if (t < o) sh[t] += sh[t + o];
        __syncthreads();
    }
    if (t == 0) {
        float m = (float)(sh[0] / 16777216.0);
        out[LOSS_OFF] = __fadd_rn(m, __fmul_rn(0.25f, m));
    }
}

// ---------------- gather ----------------
__global__ void k_gather(const float* __restrict__ cb, float* __restrict__ out) {
    __shared__ float sm[32][257];
    __shared__ int js[32];
    const int i0 = blockIdx.x * 32;
    const int b  = i0 >> 12;
    const int p0 = i0 & 4095;
    const int t  = threadIdx.x;

    if (t < 32) js[t] = d_sidx[i0 + t];
    __syncthreads();
#pragma unroll
    for (int s = t; s < 32 * 256; s += 256) {
        int row = s >> 8, col = s & 255;
        sm[row][col] = cb[(size_t)js[row] * CDIM + col];
    }
    __syncthreads();
    float* ob = out + ((size_t)b << 20) + p0;
#pragma unroll
    for (int c0 = 0; c0 < 256; c0 += 8) {
        int c = c0 + (t >> 5);
        int p = t & 31;
        ob[((size_t)c << 12) + p] = sm[p][c];
    }
    if (t < 32) out[IDX_OFF + i0 + t] = (float)js[t];
}

// ---------------- launch ----------------
extern "C" void kernel_launch(void* const* d_in, const int* in_sizes, int n_in,
                              void* d_out, int out_size) {
    const float* z  = (const float*)d_in[0];
    const float* cb = (const float*)d_in[1];
    float* out = (float*)d_out;

    cudaFuncSetAttribute(k_main_mma, cudaFuncAttributeMaxDynamicSharedMemorySize, SM_TOTAL);

    k_prep<<<NE, 256>>>(cb);
    k_convert<<<dim3(8, 128, 16), dim3(32, 8)>>>(z);
    k_main_mma<<<NVEC / 64, 128, SM_TOTAL>>>();
    k_rescore<<<512, 256>>>(z, cb);
    k_loss2<<<1, 256>>>(out);
    k_gather<<<NVEC / 32, 256>>>(cb, out);
}

// round 17
// speedup vs baseline: 1.4732x; 1.4732x over previous
#include <cuda_runtime.h>
#include <cuda_fp16.h>
#include <cstdint>
#include <float.h>

#define CDIM 256
#define HW   4096
#define NVEC 65536
#define NE   1024
#define LOSS_OFF 16777216
#define IDX_OFF  16777217
#define TAU      2.5e-4f     // fp32 gap-ambiguity threshold (proven R9-R15)
#define TAU_SCAN 4e-4f       // candidate scan limit vs fp16-dumped s (superset)

// ---------------- scratch ----------------
__device__ __half d_zh[(size_t)NVEC * CDIM];
__device__ __half d_ch[NE * CDIM];
__device__ __half d_sh[(size_t)NVEC * NE];   // fp16 s matrix (128MB)
__device__ float d_cnorm[NE];
__device__ float d_zn[NVEC];
__device__ float d_smin[NVEC];
__device__ int   d_sidx[NVEC];
__device__ int   d_cand[(size_t)NVEC * 48];
__device__ int   d_amb[NVEC];
__device__ int   d_count;
__device__ double d_part[256];

// ---------------- PTX helpers ----------------
__device__ __forceinline__ unsigned smem_u32(const void* p) {
    return (unsigned)__cvta_generic_to_shared(p);
}
__device__ __forceinline__ void cp_async16(unsigned s, const void* g) {
    asm volatile("cp.async.cg.shared.global [%0], [%1], 16;\n" :: "r"(s), "l"(g));
}
__device__ __forceinline__ void cp_commit() {
    asm volatile("cp.async.commit_group;\n" ::: "memory");
}
__device__ __forceinline__ void cp_wait0() {
    asm volatile("cp.async.wait_group 0;\n" ::: "memory");
}
__device__ __forceinline__ void ldsm4(unsigned* r, unsigned addr) {
    asm volatile("ldmatrix.sync.aligned.m8n8.x4.shared.b16 {%0,%1,%2,%3}, [%4];"
                 : "=r"(r[0]), "=r"(r[1]), "=r"(r[2]), "=r"(r[3]) : "r"(addr));
}
__device__ __forceinline__ void mma16816(float* d, const unsigned* a,
                                         unsigned b0, unsigned b1) {
    asm volatile(
        "mma.sync.aligned.m16n8k16.row.col.f32.f16.f16.f32 "
        "{%0,%1,%2,%3}, {%4,%5,%6,%7}, {%8,%9}, {%0,%1,%2,%3};"
        : "+f"(d[0]), "+f"(d[1]), "+f"(d[2]), "+f"(d[3])
        : "r"(a[0]), "r"(a[1]), "r"(a[2]), "r"(a[3]), "r"(b0), "r"(b1));
}
__device__ __forceinline__ void stg_cs32(void* p, unsigned v) {
    asm volatile("st.global.cs.b32 [%0], %1;" :: "l"(p), "r"(v) : "memory");
}
__device__ __forceinline__ void stg_cs32f(float* p, float v) {
    asm volatile("st.global.cs.f32 [%0], %1;" :: "l"(p), "f"(v) : "memory");
}

__device__ __forceinline__ void ins2(float s, int j, float& v0, int& i0,
                                     float& v1, int& i1) {
    if (s < v0 || (s == v0 && j < i0)) { v1 = v0; i1 = i0; v0 = s; i0 = j; }
    else if (s < v1 || (s == v1 && j < i1)) { v1 = s; i1 = j; }
}

// ---------------- prep: codebook fp16 + exact norms + zeroing --------------
__global__ void k_prep(const float* __restrict__ cb) {
    __shared__ float rowv[256];
    int j = blockIdx.x, k = threadIdx.x;
    float v = cb[j * CDIM + k];
    rowv[k] = v;
    d_ch[j * CDIM + k] = __float2half(v);
    int idx = j * 256 + k;
    if (idx < NVEC) d_zn[idx] = 0.f;
    if (idx == 0) d_count = 0;
    if (j == 0) d_part[k] = 0.0;
    __syncthreads();
    if (k == 0) {                       // exact sequential chain, ascending k
        float s = 0.f;
        for (int kk = 0; kk < CDIM; ++kk)
            s = __fadd_rn(s, __fmul_rn(rowv[kk], rowv[kk]));
        d_cnorm[j] = s;
    }
}

// ---------------- kernel: z transpose -> fp16 [i][k], fused znorm ----------
__global__ void k_convert(const float* __restrict__ z) {
    __shared__ float t[32][33];
    int k0 = blockIdx.x * 32, p0 = blockIdx.y * 32, b = blockIdx.z;
    int x = threadIdx.x, y = threadIdx.y;
#pragma unroll
    for (int yy = y; yy < 32; yy += 8)
        t[yy][x] = z[((size_t)b << 20) + ((size_t)(k0 + yy) << 12) + p0 + x];
    __syncthreads();
#pragma unroll
    for (int yy = y; yy < 32; yy += 8) {
        float v = t[x][yy];
        size_t i = ((size_t)b << 12) + p0 + yy;
        d_zh[i * CDIM + k0 + x] = __float2half(v);
        float sq = v * v;
#pragma unroll
        for (int o = 16; o; o >>= 1) sq += __shfl_xor_sync(0xffffffffu, sq, o);
        if (x == 0) atomicAdd(&d_zn[i], sq);
    }
}

// ---------------- main: fp16 HMMA + s dump + fused top-2 + loss partial ----
#define SM_A   0u
#define SM_B   32768u      // 2 x 16KB
#define SM_RED 65536u
#define SM_TOTAL 66560

__device__ __forceinline__ void stageB(int tid, int g, unsigned dstb) {
    const int ntc = g >> 2, kcc = g & 3;
#pragma unroll
    for (int q = 0; q < 8; ++q) {
        int u = q * 128 + tid;
        int r = u >> 3, w = u & 7;
        unsigned dst = (unsigned)(r * 128 + ((w * 16) ^ ((r & 7) << 4)));
        cp_async16(dstb + dst, d_ch + (size_t)(ntc * 128 + r) * CDIM + kcc * 64 + w * 8);
    }
}

__global__ __launch_bounds__(128, 3) void k_main_mma() {
    extern __shared__ __align__(128) char smem[];
    const unsigned sb = smem_u32(smem);
    const int tid = threadIdx.x, wid = tid >> 5, lane = tid & 31;
    const int m0 = blockIdx.x * 64;
    const int mb = (wid >> 1) * 32;
    const int nb = (wid & 1) * 64;

    // ---- hoisted swizzled LDSM offsets ----
    unsigned aOff0[4], aOff1[4], bOff[4][4];
    {
        const unsigned hiA = (unsigned)((lane >> 4) << 4);
        const int ar0 = mb + (lane & 15);
        const int ar1 = ar0 + 16;
#pragma unroll
        for (int ks = 0; ks < 4; ++ks) {
            aOff0[ks] = (unsigned)(ar0 * 512) + (((unsigned)(ks * 32) + hiA) ^ ((unsigned)(ar0 & 7) << 4));
            aOff1[ks] = (unsigned)(ar1 * 512) + (((unsigned)(ks * 32) + hiA) ^ ((unsigned)(ar1 & 7) << 4));
        }
        const unsigned hiB = (unsigned)(((lane >> 3) & 1) << 4);
#pragma unroll
        for (int p = 0; p < 4; ++p) {
            int br = nb + p * 16 + (lane & 7) + ((lane >> 4) << 3);
#pragma unroll
            for (int ks = 0; ks < 4; ++ks)
                bOff[p][ks] = (unsigned)(br * 128) + (((unsigned)(ks * 32) + hiB) ^ ((unsigned)(br & 7) << 4));
        }
    }

    // prologue: A (64 rows x 512B) + B chunk0
#pragma unroll
    for (int q = 0; q < 16; ++q) {
        int u = q * 128 + tid;
        int r = u >> 5, w = u & 31;
        unsigned dst = (unsigned)(r * 512 + ((w * 16) ^ ((r & 7) << 4)));
        cp_async16(sb + SM_A + dst, d_zh + (size_t)(m0 + r) * CDIM + w * 8);
    }
    stageB(tid, 0, sb + SM_B);
    cp_commit();

    __half* sOutBase = d_sh + (size_t)(m0 + mb + (lane >> 2)) * NE + nb + (lane & 3) * 2;

    float gv0[4], gv1[4];
    int   gi0[4], gi1[4];
#pragma unroll
    for (int q = 0; q < 4; ++q) {
        gv0[q] = FLT_MAX; gv1[q] = FLT_MAX;
        gi0[q] = 0x7fffffff; gi1[q] = 0x7fffffff;
    }

    float acc[2][8][4];
#pragma unroll
    for (int m = 0; m < 2; ++m)
#pragma unroll
        for (int f = 0; f < 8; ++f)
#pragma unroll
            for (int e = 0; e < 4; ++e) acc[m][f][e] = 0.f;

    for (int g = 0; g < 32; ++g) {
        cp_wait0();
        __syncthreads();
        if (g + 1 < 32) {
            stageB(tid, g + 1, sb + SM_B + (unsigned)((g + 1) & 1) * 16384u);
            cp_commit();
        }

        const unsigned aB = sb + (unsigned)((g & 3) * 128);
        const unsigned bB = sb + SM_B + (unsigned)((g & 1) * 16384);
#pragma unroll
        for (int ks = 0; ks < 4; ++ks) {
            unsigned af[8], bf[16];
            ldsm4(af,     aB + aOff0[ks]);
            ldsm4(af + 4, aB + aOff1[ks]);
#pragma unroll
            for (int p = 0; p < 4; ++p)
                ldsm4(bf + p * 4, bB + bOff[p][ks]);
#pragma unroll
            for (int p = 0; p < 4; ++p) {
                mma16816(acc[0][2 * p],     af,     bf[p * 4],     bf[p * 4 + 1]);
                mma16816(acc[0][2 * p + 1], af,     bf[p * 4 + 2], bf[p * 4 + 3]);
                mma16816(acc[1][2 * p],     af + 4, bf[p * 4],     bf[p * 4 + 1]);
                mma16816(acc[1][2 * p + 1], af + 4, bf[p * 4 + 2], bf[p * 4 + 3]);
            }
        }

        if ((g & 3) == 3) {
            const int j0 = (g >> 2) * 128;
            float cn0[8], cn1[8];
            int   colf[8];
#pragma unroll
            for (int f = 0; f < 8; ++f) {
                int col = j0 + nb + (f >> 1) * 16 + (f & 1) * 8 + (lane & 3) * 2;
                colf[f] = col;
                cn0[f] = __ldg(&d_cnorm[col]);
                cn1[f] = __ldg(&d_cnorm[col + 1]);
            }
#pragma unroll
            for (int m = 0; m < 2; ++m) {
#pragma unroll
                for (int hl = 0; hl < 2; ++hl) {
                    const int q = m * 2 + hl;
                    __half* ro = sOutBase + (size_t)(m * 16 + hl * 8) * NE + j0;
#pragma unroll
                    for (int f = 0; f < 8; ++f) {
                        float s0 = __fmaf_rn(-2.f, acc[m][f][hl * 2 + 0], cn0[f]);
                        float s1 = __fmaf_rn(-2.f, acc[m][f][hl * 2 + 1], cn1[f]);
                        __half2 h2 = __floats2half2_rn(s0, s1);
                        stg_cs32(ro + (f >> 1) * 16 + (f & 1) * 8,
                                 *(unsigned*)&h2);
                        ins2(s0, colf[f],     gv0[q], gi0[q], gv1[q], gi1[q]);
                        ins2(s1, colf[f] + 1, gv0[q], gi0[q], gv1[q], gi1[q]);
                    }
                }
            }
#pragma unroll
            for (int m = 0; m < 2; ++m)
#pragma unroll
                for (int f = 0; f < 8; ++f)
#pragma unroll
                    for (int e = 0; e < 4; ++e) acc[m][f][e] = 0.f;
        }
    }

    // ---- quad merge (lanes sharing a row) ----
#pragma unroll
    for (int q = 0; q < 4; ++q) {
#pragma unroll
        for (int o = 1; o <= 2; o <<= 1) {
            float w0 = __shfl_xor_sync(0xffffffffu, gv0[q], o);
            int   wi0 = __shfl_xor_sync(0xffffffffu, gi0[q], o);
            float w1 = __shfl_xor_sync(0xffffffffu, gv1[q], o);
            int   wi1 = __shfl_xor_sync(0xffffffffu, gi1[q], o);
            ins2(w0, wi0, gv0[q], gi0[q], gv1[q], gi1[q]);
            ins2(w1, wi1, gv0[q], gi0[q], gv1[q], gi1[q]);
        }
    }

    // ---- cross-warp (N-half) merge via smem (64 rows) + loss partial ----
    float* rv0 = (float*)(smem + SM_RED);
    float* rv1 = rv0 + 64;
    int*   ri0 = (int*)(rv1 + 64);
    int*   ri1 = ri0 + 64;
    __syncthreads();
    if ((wid & 1) == 1 && (lane & 3) == 0) {
#pragma unroll
        for (int q = 0; q < 4; ++q) {
            int rl = mb + (q >> 1) * 16 + (q & 1) * 8 + (lane >> 2);
            rv0[rl] = gv0[q]; ri0[rl] = gi0[q];
            rv1[rl] = gv1[q]; ri1[rl] = gi1[q];
        }
    }
    __syncthreads();
    if ((wid & 1) == 0 && (lane & 3) == 0) {
        double lsum = 0.0;
#pragma unroll
        for (int q = 0; q < 4; ++q) {
            int rl = mb + (q >> 1) * 16 + (q & 1) * 8 + (lane >> 2);
            ins2(rv0[rl], ri0[rl], gv0[q], gi0[q], gv1[q], gi1[q]);
            ins2(rv1[rl], ri1[rl], gv0[q], gi0[q], gv1[q], gi1[q]);
            int row = m0 + rl;
            d_smin[row] = gv0[q];
            d_sidx[row] = gi0[q];
            lsum += (double)d_zn[row] + (double)gv0[q];
            if (gv1[q] - gv0[q] < TAU)
                d_amb[atomicAdd(&d_count, 1)] = row;
        }
        atomicAdd(&d_part[blockIdx.x & 255], lsum);
    }
}

// ---------------- rescore: grid-stride; candidate scan + exact chains ------
// (R15 version — direct broadcast z reads; smem staging regressed in R16.)
// Updates d_sidx ONLY (d_smin keeps approx value for the loss).
__global__ void k_rescore(const float* __restrict__ z, const float* __restrict__ cb) {
    const int lane = threadIdx.x & 31;
    const int warp0 = (blockIdx.x * blockDim.x + threadIdx.x) >> 5;
    const int nwarps = (gridDim.x * blockDim.x) >> 5;
    const int cnt = d_count;

    for (int wi = warp0; wi < cnt; wi += nwarps) {
        int row = d_amb[wi];

        // ---- compact candidates: all j with s_fp16 < smin + TAU_SCAN ----
        {
            const float limit = d_smin[row] + TAU_SCAN;
            const __half2* srow = (const __half2*)(d_sh + (size_t)row * NE);
            const int winner = d_sidx[row];
            int base = 0;
#pragma unroll
            for (int it = 0; it < 16; ++it) {
                float2 s2 = __half22float2(srow[it * 32 + lane]);
#pragma unroll
                for (int e = 0; e < 2; ++e) {
                    bool take = (e ? s2.y : s2.x) < limit;
                    unsigned msk = __ballot_sync(0xffffffffu, take);
                    int pos = base + __popc(msk & ((1u << lane) - 1u));
                    if (take && pos < 48)
                        d_cand[(size_t)row * 48 + pos] = (it * 32 + lane) * 2 + e;
                    base += __popc(msk);
                }
            }
            if (base > 48) base = 48;
            for (int q = base + lane; q < 48; q += 32)
                d_cand[(size_t)row * 48 + q] = winner;
            __syncwarp();
        }

        int b = row >> 12, p = row & 4095;
        const float* zbase = z + ((size_t)b << 20) + p;

        int ja = d_cand[(size_t)row * 48 + lane] & 1023;
        int jb = (lane < 16) ? (d_cand[(size_t)row * 48 + 32 + lane] & 1023) : ja;
        const float* ca = cb + (size_t)ja * CDIM;
        const float* cbr = cb + (size_t)jb * CDIM;

        float zn = 0.f, da = 0.f, db = 0.f;
        for (int k = 0; k < CDIM; ++k) {        // strictly ascending k
            float zv = zbase[(size_t)k << 12];  // broadcast across warp
            zn = __fadd_rn(zn, __fmul_rn(zv, zv));
            da = __fmaf_rn(zv, ca[k], da);
            db = __fmaf_rn(zv, cbr[k], db);
        }
        float ea = __fadd_rn(__fadd_rn(zn, d_cnorm[ja]), -(2.0f * da));
        float eb = __fadd_rn(__fadd_rn(zn, d_cnorm[jb]), -(2.0f * db));

        float v = ea; int vi = ja;
        if (lane < 16 && (eb < v || (eb == v && jb < vi))) { v = eb; vi = jb; }
#pragma unroll
        for (int o = 16; o; o >>= 1) {
            float v2 = __shfl_xor_sync(0xffffffffu, v, o);
            int   i2 = __shfl_xor_sync(0xffffffffu, vi, o);
            if (v2 < v || (v2 == v && i2 < vi)) { v = v2; vi = i2; }
        }
        if (lane == 0) {
            d_sidx[row] = vi;
        }
    }
}

// ---------------- loss final (fp64 partials from k_main) ----------------
__global__ void k_loss2(float* __restrict__ out) {
    __shared__ double sh[256];
    const int t = threadIdx.x;
    sh[t] = d_part[t];
    __syncthreads();
#pragma unroll
    for (int o = 128; o; o >>= 1) {
        if (t < o) sh[t] += sh[t + o];
        __syncthreads();
    }
    if (t == 0) {
        float m = (float)(sh[0] / 16777216.0);
        out[LOSS_OFF] = __fadd_rn(m, __fmul_rn(0.25f, m));
    }
}

// ---------------- gather (output streamed with .cs) ----------------
__global__ void k_gather(const float* __restrict__ cb, float* __restrict__ out) {
    __shared__ float sm[32][257];
    __shared__ int js[32];
    const int i0 = blockIdx.x * 32;
    const int b  = i0 >> 12;
    const int p0 = i0 & 4095;
    const int t  = threadIdx.x;

    if (t < 32) js[t] = d_sidx[i0 + t];
    __syncthreads();
#pragma unroll
    for (int s = t; s < 32 * 256; s += 256) {
        int row = s >> 8, col = s & 255;
        sm[row][col] = cb[(size_t)js[row] * CDIM + col];
    }
    __syncthreads();
    float* ob = out + ((size_t)b << 20) + p0;
#pragma unroll
    for (int c0 = 0; c0 < 256; c0 += 8) {
        int c = c0 + (t >> 5);
        int p = t & 31;
        stg_cs32f(ob + ((size_t)c << 12) + p, sm[p][c]);
    }
    if (t < 32) out[IDX_OFF + i0 + t] = (float)js[t];
}

// ---------------- launch ----------------
extern "C" void kernel_launch(void* const* d_in, const int* in_sizes, int n_in,
                              void* d_out, int out_size) {
    const float* z  = (const float*)d_in[0];
    const float* cb = (const float*)d_in[1];
    float* out = (float*)d_out;

    cudaFuncSetAttribute(k_main_mma, cudaFuncAttributeMaxDynamicSharedMemorySize, SM_TOTAL);

    k_prep<<<NE, 256>>>(cb);
    k_convert<<<dim3(8, 128, 16), dim3(32, 8)>>>(z);
    k_main_mma<<<NVEC / 64, 128, SM_TOTAL>>>();
    k_rescore<<<512, 256>>>(z, cb);
    k_loss2<<<1, 256>>>(out);
    k_gather<<<NVEC / 32, 256>>>(cb, out);
}